// round 14
// baseline (speedup 1.0000x reference)
#include <cuda_runtime.h>
#include <cuda_bf16.h>
#include <cuda_fp16.h>
#include <math.h>
#include <stdint.h>

#define N_NODESC 100000
#define N_EDGESC 1600000
#define HID 128
#define NGRAPH 256
#define NLAYER 3
#define SCAN_BLOCKS ((N_NODESC + 1023) / 1024)   // 98
#define NT64 ((N_NODESC + 63) / 64)              // 1563
#define AGG_BLOCKS ((N_NODESC * 32 + 255) / 256) // 12500

// prep kernel block ranges (W-split | zero-counts only)
#define WB ((NLAYER * HID * HID + 255) / 256)    // 192
#define ZB ((N_NODESC + 256) / 256)              // 392

// ---------------- scratch (static device globals; no allocation) ----------------
__device__ __half    g_h[2][(size_t)N_NODESC * HID];   // GEMM output (fp16)
__device__ uint32_t  g_xs[2][(size_t)N_NODESC * HID];  // activations, packed bf16 hi|lo
__device__ uint32_t  g_ws[2][NLAYER * HID * HID];      // W, packed bf16 hi|lo
__device__ float     g_dis[2][N_NODESC];
__device__ int       g_off[2][N_NODESC + 1];
__device__ int       g_cur[2][N_NODESC];
__device__ int2      g_ew[2][N_EDGESC];                // {src, enorm}
__device__ int       g_bsum[2][SCAN_BLOCKS + 1];
__device__ float     g_z[NGRAPH * HID];
__device__ float     g_scn[NGRAPH * HID];
__device__ float     g_fcn[NGRAPH * HID];
__device__ float     g_loss[2 * NGRAPH];

// ---------------- helpers ----------------
__device__ __forceinline__ uint32_t smem_u32(const void* p) {
    uint32_t a;
    asm("{ .reg .u64 t; cvta.to.shared.u64 t, %1; cvt.u32.u64 %0, t; }"
        : "=r"(a) : "l"(p));
    return a;
}
__device__ __forceinline__ uint32_t packsplit(float v) {
    __nv_bfloat16 h = __float2bfloat16_rn(v);
    float lo = v - __bfloat162float(h);
    __nv_bfloat16 l = __float2bfloat16_rn(lo);
    return (uint32_t)__bfloat16_as_ushort(h) |
           ((uint32_t)__bfloat16_as_ushort(l) << 16);
}
__device__ __forceinline__ float unpacksplit(uint32_t p) {
    return __bfloat162float(__ushort_as_bfloat16((unsigned short)(p & 0xffffu))) +
           __bfloat162float(__ushort_as_bfloat16((unsigned short)(p >> 16)));
}
#define LDSM_X4(r0, r1, r2, r3, addr) \
    asm volatile("ldmatrix.sync.aligned.m8n8.x4.shared.b16 {%0,%1,%2,%3}, [%4];" \
                 : "=r"(r0), "=r"(r1), "=r"(r2), "=r"(r3) : "r"(addr))
#define LDSM_X4T(r0, r1, r2, r3, addr) \
    asm volatile("ldmatrix.sync.aligned.m8n8.x4.trans.shared.b16 {%0,%1,%2,%3}, [%4];" \
                 : "=r"(r0), "=r"(r1), "=r"(r2), "=r"(r3) : "r"(addr))
#define MMA16816(c, a, b0, b1) \
    asm volatile("mma.sync.aligned.m16n8k16.row.col.f32.bf16.bf16.f32 " \
                 "{%0,%1,%2,%3}, {%4,%5,%6,%7}, {%8,%9}, {%0,%1,%2,%3};" \
                 : "+f"((c)[0]), "+f"((c)[1]), "+f"((c)[2]), "+f"((c)[3]) \
                 : "r"((a)[0]), "r"((a)[1]), "r"((a)[2]), "r"((a)[3]), \
                   "r"(b0), "r"(b1))

// ---------------- prep: w-split | zero counts (both branches) ----------------
__global__ void k_prep(const float* __restrict__ scW, const float* __restrict__ fcW) {
    int b = blockIdx.y;
    int bx = blockIdx.x;
    if (bx < WB) {
        const float* W = b ? fcW : scW;
        int i = bx * 256 + threadIdx.x;
        if (i < NLAYER * HID * HID) g_ws[b][i] = packsplit(W[i]);
    } else {
        int i = (bx - WB) * 256 + threadIdx.x;
        if (i <= N_NODESC) g_off[b][i] = 0;
    }
}

// ---------------- CSR build (both branches) ----------------
__global__ void k_hist(const int* __restrict__ sc_ei, const int* __restrict__ fc_ei) {
    int b = blockIdx.y;
    const int* dst = (b ? fc_ei : sc_ei) + N_EDGESC;
    for (int e = blockIdx.x * blockDim.x + threadIdx.x; e < N_EDGESC;
         e += gridDim.x * blockDim.x)
        atomicAdd(&g_off[b][dst[e]], 1);
}
__global__ void k_scan1() {
    __shared__ int ws[32];
    int b = blockIdx.y;
    int t = threadIdx.x;
    int lane = t & 31, w = t >> 5;
    int idx = blockIdx.x * 1024 + t;
    int v = (idx < N_NODESC) ? g_off[b][idx] : 0;
    if (idx < N_NODESC) g_dis[b][idx] = rsqrtf((float)v + 1.0f);
    int x = v;
#pragma unroll
    for (int off = 1; off < 32; off <<= 1) {
        int n = __shfl_up_sync(0xffffffffu, x, off);
        if (lane >= off) x += n;
    }
    if (lane == 31) ws[w] = x;
    __syncthreads();
    if (w == 0) {
        int y = ws[lane];
#pragma unroll
        for (int off = 1; off < 32; off <<= 1) {
            int n = __shfl_up_sync(0xffffffffu, y, off);
            if (lane >= off) y += n;
        }
        ws[lane] = y;
    }
    __syncthreads();
    int inc = x + ((w > 0) ? ws[w - 1] : 0);
    if (idx < N_NODESC) g_off[b][idx] = inc - v;
    if (t == 1023) g_bsum[b][blockIdx.x] = inc;
}
__global__ void k_scan3() {
    int b = blockIdx.y;
    int t = threadIdx.x;
    __shared__ int wsum[32];
    __shared__ int s_pref;
    int lane = t & 31, w = t >> 5;
    int v = (t < blockIdx.x) ? g_bsum[b][t] : 0;
#pragma unroll
    for (int off = 16; off > 0; off >>= 1)
        v += __shfl_down_sync(0xffffffffu, v, off);
    if (lane == 0) wsum[w] = v;
    __syncthreads();
    if (t == 0) {
        int s = 0;
#pragma unroll
        for (int i = 0; i < 32; i++) s += wsum[i];
        s_pref = s;
    }
    __syncthreads();
    int idx = blockIdx.x * 1024 + t;
    if (idx < N_NODESC) {
        int o = g_off[b][idx] + s_pref;
        g_off[b][idx] = o;
        g_cur[b][idx] = o;
    }
    if (blockIdx.x == 0 && t == 0) g_off[b][N_NODESC] = N_EDGESC;
}
__global__ void k_bucket(const int* __restrict__ sc_ei, const int* __restrict__ fc_ei) {
    int b = blockIdx.y;
    const int* src = (b ? fc_ei : sc_ei);
    const int* dst = src + N_EDGESC;
    for (int e = blockIdx.x * blockDim.x + threadIdx.x; e < N_EDGESC;
         e += gridDim.x * blockDim.x) {
        int d = dst[e];
        int s = src[e];
        int slot = atomicAdd(&g_cur[b][d], 1);
        float w = g_dis[b][s] * g_dis[b][d];
        g_ew[b][slot] = make_int2(s, __float_as_int(w));
    }
}

// ---------------- persistent tensor-core GEMM (single branch, param b) ----------
#define APITCH 136
#define BTILE_B (128 * APITCH * 2)     // 34816
#define ATILE_B (64 * APITCH * 2)      // 17408
#define OFF_BHI 0
#define OFF_BLO BTILE_B
#define OFF_AHI (2 * BTILE_B)
#define OFF_ALO (2 * BTILE_B + ATILE_B)
#define GEMM_SMEM (2 * BTILE_B + 2 * ATILE_B)   // 104448

template <bool L0>
__global__ void __launch_bounds__(256, 2)
k_gemm_mma(int b, int layer, int nrows, const float4* __restrict__ xf) {
    extern __shared__ char sm[];
    uint32_t base = smem_u32(sm);
    int tid = threadIdx.x;
    const uint32_t* Xp = g_xs[b];
    const float4* Xf = xf;
    const uint32_t* Wp = g_ws[b] + layer * HID * HID;
    __half* Hp = g_h[b];

    for (int g = tid; g < 128 * 32; g += 256) {
        int k = g >> 5, q = g & 31;
        uint4 p = ((const uint4*)Wp)[k * 32 + q];
        uint32_t off = (uint32_t)(k * APITCH + q * 4) * 2u;
        *(uint2*)(sm + OFF_BHI + off) =
            make_uint2(__byte_perm(p.x, p.y, 0x5410), __byte_perm(p.z, p.w, 0x5410));
        *(uint2*)(sm + OFF_BLO + off) =
            make_uint2(__byte_perm(p.x, p.y, 0x7632), __byte_perm(p.z, p.w, 0x7632));
    }

    int w = tid >> 5, lane = tid & 31;
    int wm = w & 1, wn = w >> 1;
    int rbase = wm * 32, cbase = wn * 32;
    int a_r = lane & 15, a_c = (lane >> 4) * 8;
    int b_kr = ((lane >> 3) & 1) * 8 + (lane & 7), b_c = (lane >> 4) * 8;

    uint4 pre[8];
    {
        int r0 = blockIdx.x * 64;
#pragma unroll
        for (int i = 0; i < 8; ++i) {
            int g = tid + i * 256;
            int row = g >> 5, q = g & 31;
            int grow = r0 + row;
            if (grow < nrows) {
                if (L0) {
                    float4 v = Xf[(size_t)grow * 32 + q];
                    pre[i] = *(uint4*)&v;
                } else {
                    pre[i] = ((const uint4*)(Xp + (size_t)grow * HID))[q];
                }
            } else {
                pre[i] = make_uint4(0u, 0u, 0u, 0u);
            }
        }
    }

    for (int tile = blockIdx.x; tile < NT64; tile += gridDim.x) {
        int r0 = tile * 64;
        __syncthreads();
#pragma unroll
        for (int i = 0; i < 8; ++i) {
            int g = tid + i * 256;
            int row = g >> 5, q = g & 31;
            uint4 p;
            if (L0) {
                float4 v = *(float4*)&pre[i];
                p = make_uint4(packsplit(v.x), packsplit(v.y),
                               packsplit(v.z), packsplit(v.w));
            } else {
                p = pre[i];
            }
            uint32_t off = (uint32_t)(row * APITCH + q * 4) * 2u;
            *(uint2*)(sm + OFF_AHI + off) =
                make_uint2(__byte_perm(p.x, p.y, 0x5410), __byte_perm(p.z, p.w, 0x5410));
            *(uint2*)(sm + OFF_ALO + off) =
                make_uint2(__byte_perm(p.x, p.y, 0x7632), __byte_perm(p.z, p.w, 0x7632));
        }
        __syncthreads();

        int next = tile + gridDim.x;
        if (next < NT64) {
            int nr0 = next * 64;
#pragma unroll
            for (int i = 0; i < 8; ++i) {
                int g = tid + i * 256;
                int row = g >> 5, q = g & 31;
                int grow = nr0 + row;
                if (grow < nrows) {
                    if (L0) {
                        float4 v = Xf[(size_t)grow * 32 + q];
                        pre[i] = *(uint4*)&v;
                    } else {
                        pre[i] = ((const uint4*)(Xp + (size_t)grow * HID))[q];
                    }
                } else {
                    pre[i] = make_uint4(0u, 0u, 0u, 0u);
                }
            }
        }

        float acc[2][4][4];
#pragma unroll
        for (int m = 0; m < 2; m++)
#pragma unroll
            for (int n = 0; n < 4; n++)
#pragma unroll
                for (int c = 0; c < 4; c++) acc[m][n][c] = 0.f;

#pragma unroll
        for (int ks = 0; ks < 8; ++ks) {
            int k0 = ks * 16;
            uint32_t ahi[2][4], alo[2][4];
#pragma unroll
            for (int m = 0; m < 2; ++m) {
                uint32_t aoff =
                    (uint32_t)((rbase + m * 16 + a_r) * APITCH + k0 + a_c) * 2u;
                LDSM_X4(ahi[m][0], ahi[m][1], ahi[m][2], ahi[m][3], base + OFF_AHI + aoff);
                LDSM_X4(alo[m][0], alo[m][1], alo[m][2], alo[m][3], base + OFF_ALO + aoff);
            }
#pragma unroll
            for (int n2 = 0; n2 < 2; ++n2) {
                int n0 = cbase + n2 * 16;
                uint32_t boff = (uint32_t)((k0 + b_kr) * APITCH + n0 + b_c) * 2u;
                uint32_t bh0, bh1, bh2, bh3, bl0, bl1, bl2, bl3;
                LDSM_X4T(bh0, bh1, bh2, bh3, base + OFF_BHI + boff);
                LDSM_X4T(bl0, bl1, bl2, bl3, base + OFF_BLO + boff);
#pragma unroll
                for (int m = 0; m < 2; ++m) {
                    MMA16816(acc[m][n2 * 2], ahi[m], bh0, bh1);
                    MMA16816(acc[m][n2 * 2 + 1], ahi[m], bh2, bh3);
                    MMA16816(acc[m][n2 * 2], ahi[m], bl0, bl1);
                    MMA16816(acc[m][n2 * 2 + 1], ahi[m], bl2, bl3);
                    MMA16816(acc[m][n2 * 2], alo[m], bh0, bh1);
                    MMA16816(acc[m][n2 * 2 + 1], alo[m], bh2, bh3);
                }
            }
        }

#pragma unroll
        for (int m = 0; m < 2; ++m) {
            int rA = r0 + rbase + m * 16 + (lane >> 2);
            int rB = rA + 8;
#pragma unroll
            for (int ng = 0; ng < 4; ++ng) {
                int col = cbase + ng * 8 + (lane & 3) * 2;
                if (rA < nrows)
                    *(__half2*)(Hp + (size_t)rA * HID + col) =
                        __floats2half2_rn(acc[m][ng][0], acc[m][ng][1]);
                if (rB < nrows)
                    *(__half2*)(Hp + (size_t)rB * HID + col) =
                        __floats2half2_rn(acc[m][ng][2], acc[m][ng][3]);
            }
        }
    }
}

// ---------------- fused aggregation (single branch, param b) ----------------
__global__ void __launch_bounds__(256)
k_agg(int b, const float* __restrict__ bias0, int layer) {
    int node = (blockIdx.x * blockDim.x + threadIdx.x) >> 5;
    int lane = threadIdx.x & 31;
    if (node >= N_NODESC) return;
    const __half* Hp = g_h[b];
    const int2* ew = g_ew[b];
    const float* bias = bias0 + layer * HID;
    float dd = g_dis[b][node];
    int beg = g_off[b][node], end = g_off[b][node + 1];
    float ax = 0.f, ay = 0.f, az = 0.f, aw = 0.f;
    int e = beg;
    for (; e + 3 < end; e += 4) {
        int2 p0 = ew[e], p1 = ew[e + 1], p2 = ew[e + 2], p3 = ew[e + 3];
        uint2 r0v = *(const uint2*)(Hp + (size_t)p0.x * HID + lane * 4);
        uint2 r1v = *(const uint2*)(Hp + (size_t)p1.x * HID + lane * 4);
        uint2 r2v = *(const uint2*)(Hp + (size_t)p2.x * HID + lane * 4);
        uint2 r3v = *(const uint2*)(Hp + (size_t)p3.x * HID + lane * 4);
        float w0 = __int_as_float(p0.y), w1 = __int_as_float(p1.y);
        float w2 = __int_as_float(p2.y), w3 = __int_as_float(p3.y);
        float2 f0 = __half22float2(*(__half2*)&r0v.x);
        float2 f1 = __half22float2(*(__half2*)&r0v.y);
        ax = fmaf(f0.x, w0, ax); ay = fmaf(f0.y, w0, ay);
        az = fmaf(f1.x, w0, az); aw = fmaf(f1.y, w0, aw);
        f0 = __half22float2(*(__half2*)&r1v.x);
        f1 = __half22float2(*(__half2*)&r1v.y);
        ax = fmaf(f0.x, w1, ax); ay = fmaf(f0.y, w1, ay);
        az = fmaf(f1.x, w1, az); aw = fmaf(f1.y, w1, aw);
        f0 = __half22float2(*(__half2*)&r2v.x);
        f1 = __half22float2(*(__half2*)&r2v.y);
        ax = fmaf(f0.x, w2, ax); ay = fmaf(f0.y, w2, ay);
        az = fmaf(f1.x, w2, az); aw = fmaf(f1.y, w2, aw);
        f0 = __half22float2(*(__half2*)&r3v.x);
        f1 = __half22float2(*(__half2*)&r3v.y);
        ax = fmaf(f0.x, w3, ax); ay = fmaf(f0.y, w3, ay);
        az = fmaf(f1.x, w3, az); aw = fmaf(f1.y, w3, aw);
    }
    for (; e < end; ++e) {
        int2 p0 = ew[e];
        float w0 = __int_as_float(p0.y);
        uint2 r0v = *(const uint2*)(Hp + (size_t)p0.x * HID + lane * 4);
        float2 f0 = __half22float2(*(__half2*)&r0v.x);
        float2 f1 = __half22float2(*(__half2*)&r0v.y);
        ax = fmaf(f0.x, w0, ax); ay = fmaf(f0.y, w0, ay);
        az = fmaf(f1.x, w0, az); aw = fmaf(f1.y, w0, aw);
    }
    uint2 rs = *(const uint2*)(Hp + (size_t)node * HID + lane * 4);
    float2 s0 = __half22float2(*(__half2*)&rs.x);
    float2 s1 = __half22float2(*(__half2*)&rs.y);
    float sn = dd * dd;
    float4 bb = *(const float4*)(bias + lane * 4);
    ax = fmaxf(fmaf(s0.x, sn, ax) + bb.x, 0.f);
    ay = fmaxf(fmaf(s0.y, sn, ay) + bb.y, 0.f);
    az = fmaxf(fmaf(s1.x, sn, az) + bb.z, 0.f);
    aw = fmaxf(fmaf(s1.y, sn, aw) + bb.w, 0.f);
    uint4 st = make_uint4(packsplit(ax), packsplit(ay), packsplit(az), packsplit(aw));
    *(uint4*)(g_xs[b] + (size_t)node * HID + lane * 4) = st;
}

// ---------------- fused pool + head: 256 threads, both branches in parallel ----
__global__ void __launch_bounds__(256)
k_headpool(const int* __restrict__ batch, const float* __restrict__ fc1W,
           const float* __restrict__ fc1b) {
    int g = blockIdx.x, t = threadIdx.x;   // 256 threads
    __shared__ int s_lo, s_hi;
    if (t == 0) {
        int lo = 0, hi = N_NODESC;
        while (lo < hi) { int m = (lo + hi) >> 1; if (batch[m] < g) lo = m + 1; else hi = m; }
        s_lo = lo;
    }
    if (t == 32) {
        int lo = 0, hi = N_NODESC;
        while (lo < hi) { int m = (lo + hi) >> 1; if (batch[m] < g + 1) lo = m + 1; else hi = m; }
        s_hi = lo;
    }
    __syncthreads();
    int lo = s_lo, hi = s_hi;
    const uint32_t* Xp = (t < 128) ? g_xs[0] : g_xs[1];
    int col = t & 127;
    float acc_p = 0.f;
    int n = lo;
    for (; n + 1 < hi; n += 2) {
        acc_p += unpacksplit(Xp[(size_t)n * HID + col]) +
                 unpacksplit(Xp[(size_t)(n + 1) * HID + col]);
    }
    for (; n < hi; ++n) acc_p += unpacksplit(Xp[(size_t)n * HID + col]);

    __shared__ float s[256];
    __shared__ float red[128];
    __shared__ float inv_ns, inv_nf;
    s[t] = acc_p;
    __syncthreads();
    if (t < 128) red[t] = s[t] * s[t];
    __syncthreads();
    for (int off = 64; off > 0; off >>= 1) {
        if (t < off) red[t] += red[t + off];
        __syncthreads();
    }
    if (t == 0) inv_ns = 1.0f / fmaxf(sqrtf(red[0]), 1e-12f);
    __syncthreads();
    if (t < 128) red[t] = s[128 + t] * s[128 + t];
    __syncthreads();
    for (int off = 64; off > 0; off >>= 1) {
        if (t < off) red[t] += red[t + off];
        __syncthreads();
    }
    if (t == 0) inv_nf = 1.0f / fmaxf(sqrtf(red[0]), 1e-12f);
    __syncthreads();
    if (t < 128) {
        float acc = 0.f;
#pragma unroll 8
        for (int k = 0; k < 256; k++) acc = fmaf(s[k], fc1W[k * HID + t], acc);
        acc += fc1b[t];
        g_z[g * HID + t] = fmaxf(acc, 0.f);
        g_scn[g * HID + t] = s[t] * inv_ns;
        g_fcn[g * HID + t] = s[128 + t] * inv_nf;
    }
}

// ---------------- contrastive row losses ----------------
__global__ void k_loss() {
    int i = blockIdx.x, j = threadIdx.x;
    __shared__ float sni[HID], fni[HID];
    __shared__ float red[256];
    __shared__ float diag_sc, diag_fc, Msc, Mfc, Ssc, Sfc;
    if (j < HID) { sni[j] = g_scn[i * HID + j]; fni[j] = g_fcn[i * HID + j]; }
    __syncthreads();
    float dsf = 0.f, dss = 0.f, dfs = 0.f, dff = 0.f;
    const float* srow = &g_scn[j * HID];
    const float* frow = &g_fcn[j * HID];
#pragma unroll 4
    for (int k = 0; k < HID; k++) {
        float sj = srow[k], fj = frow[k], si = sni[k], fi = fni[k];
        dsf = fmaf(si, fj, dsf);
        dss = fmaf(si, sj, dss);
        dfs = fmaf(fi, sj, dfs);
        dff = fmaf(fi, fj, dff);
    }
    const float tt = 2.0f;
    float e1 = dsf * tt;
    float e2 = (j == i) ? 0.f : 0.8f * tt * dss;
    float f1 = dfs * tt;
    float f2 = (j == i) ? 0.f : 0.8f * tt * dff;
    if (j == i) { diag_sc = e1; diag_fc = f1; }
    red[j] = fmaxf(e1, e2);
    __syncthreads();
    for (int off = 128; off > 0; off >>= 1) {
        if (j < off) red[j] = fmaxf(red[j], red[j + off]);
        __syncthreads();
    }
    if (j == 0) Msc = red[0];
    __syncthreads();
    red[j] = expf(e1 - Msc) + expf(e2 - Msc);
    __syncthreads();
    for (int off = 128; off > 0; off >>= 1) {
        if (j < off) red[j] += red[j + off];
        __syncthreads();
    }
    if (j == 0) Ssc = red[0];
    __syncthreads();
    red[j] = fmaxf(f1, f2);
    __syncthreads();
    for (int off = 128; off > 0; off >>= 1) {
        if (j < off) red[j] = fmaxf(red[j], red[j + off]);
        __syncthreads();
    }
    if (j == 0) Mfc = red[0];
    __syncthreads();
    red[j] = expf(f1 - Mfc) + expf(f2 - Mfc);
    __syncthreads();
    for (int off = 128; off > 0; off >>= 1) {
        if (j < off) red[j] += red[j + off];
        __syncthreads();
    }
    if (j == 0) {
        Sfc = red[0];
        g_loss[i] = (Msc + logf(Ssc)) - diag_sc;
        g_loss[NGRAPH + i] = (Mfc + logf(Sfc)) - diag_fc;
    }
}

// ---------------- final ----------------
__global__ void k_final(const float* __restrict__ fc2W, const float* __restrict__ fc2b,
                        float* __restrict__ out) {
    __shared__ float red[256];
    __shared__ float scalar;
    int t = threadIdx.x;
    red[t] = g_loss[t] + g_loss[NGRAPH + t];
    __syncthreads();
    for (int off = 128; off > 0; off >>= 1) {
        if (t < off) red[t] += red[t + off];
        __syncthreads();
    }
    if (t == 0) scalar = red[0] / (2.0f * NGRAPH);
    __syncthreads();
    float l0 = fc2b[0], l1 = fc2b[1];
    const float* z = &g_z[t * HID];
#pragma unroll 4
    for (int k = 0; k < HID; k++) {
        float zv = z[k];
        l0 = fmaf(zv, fc2W[2 * k], l0);
        l1 = fmaf(zv, fc2W[2 * k + 1], l1);
    }
    float m = fmaxf(l0, l1);
    float lse = m + logf(expf(l0 - m) + expf(l1 - m));
    out[2 * t] = l0 - lse + scalar;
    out[2 * t + 1] = l1 - lse + scalar;
}

// ---------------- host side ----------------
extern "C" void kernel_launch(void* const* d_in, const int* in_sizes, int n_in,
                              void* d_out, int out_size) {
    const float *sc_x = 0, *fc_x = 0, *sc_W = 0, *sc_b = 0, *fc_W = 0, *fc_b = 0;
    const float *fc1W = 0, *fc1b = 0, *fc2W = 0, *fc2b = 0;
    const int *sc_ei = 0, *fc_ei = 0, *batch = 0;
    for (int i = 0; i < n_in; i++) {
        long s = in_sizes[i];
        const void* p = d_in[i];
        if (s == (long)N_NODESC * HID) {
            if (!sc_x) sc_x = (const float*)p; else fc_x = (const float*)p;
        } else if (s == 2L * N_EDGESC) {
            if (!sc_ei) sc_ei = (const int*)p; else fc_ei = (const int*)p;
        } else if (s == N_NODESC) {
            batch = (const int*)p;
        } else if (s == (long)NLAYER * HID * HID) {
            if (!sc_W) sc_W = (const float*)p; else fc_W = (const float*)p;
        } else if (s == (long)NLAYER * HID) {
            if (!sc_b) sc_b = (const float*)p; else fc_b = (const float*)p;
        } else if (s == 2L * HID * HID) {
            fc1W = (const float*)p;
        } else if (s == HID) {
            fc1b = (const float*)p;
        } else if (s == 2L * HID) {
            fc2W = (const float*)p;
        } else if (s == 2) {
            fc2b = (const float*)p;
        }
    }
    cudaFuncSetAttribute(k_gemm_mma<true>, cudaFuncAttributeMaxDynamicSharedMemorySize,
                         GEMM_SMEM);
    cudaFuncSetAttribute(k_gemm_mma<false>, cudaFuncAttributeMaxDynamicSharedMemorySize,
                         GEMM_SMEM);

    cudaStream_t s2;
    cudaStreamCreateWithFlags(&s2, cudaStreamNonBlocking);
    cudaEvent_t e0, e2;
    cudaEventCreateWithFlags(&e0, cudaEventDisableTiming);
    cudaEventCreateWithFlags(&e2, cudaEventDisableTiming);

    // serial prologue on stream 0: prep + CSR (both branches)
    k_prep<<<dim3(WB + ZB, 2), 256>>>(sc_W, fc_W);
    k_hist<<<dim3(1024, 2), 256>>>(sc_ei, fc_ei);
    k_scan1<<<dim3(SCAN_BLOCKS, 2), 1024>>>();
    k_scan3<<<dim3(SCAN_BLOCKS, 2), 1024>>>();
    k_bucket<<<dim3(1024, 2), 256>>>(sc_ei, fc_ei);

    // branch 0 layer chain on stream 0; branch 1 chain on s2, offset by one phase
    k_gemm_mma<true><<<148, 256, GEMM_SMEM>>>(0, 0, N_NODESC, (const float4*)sc_x);
    cudaEventRecord(e0, 0);
    cudaStreamWaitEvent(s2, e0, 0);

    // stream s2: branch 1 full chain (gemm_l overlaps stream0's agg_l)
    k_gemm_mma<true><<<148, 256, GEMM_SMEM, s2>>>(1, 0, N_NODESC, (const float4*)fc_x);
    k_agg<<<AGG_BLOCKS, 256, 0, s2>>>(1, fc_b, 0);
    k_gemm_mma<false><<<148, 256, GEMM_SMEM, s2>>>(1, 1, N_NODESC, 0);
    k_agg<<<AGG_BLOCKS, 256, 0, s2>>>(1, fc_b, 1);
    k_gemm_mma<false><<<148, 256, GEMM_SMEM, s2>>>(1, 2, N_NODESC, 0);
    k_agg<<<AGG_BLOCKS, 256, 0, s2>>>(1, fc_b, 2);
    cudaEventRecord(e2, s2);

    // stream 0: branch 0 remainder
    k_agg<<<AGG_BLOCKS, 256>>>(0, sc_b, 0);
    k_gemm_mma<false><<<148, 256, GEMM_SMEM>>>(0, 1, N_NODESC, 0);
    k_agg<<<AGG_BLOCKS, 256>>>(0, sc_b, 1);
    k_gemm_mma<false><<<148, 256, GEMM_SMEM>>>(0, 2, N_NODESC, 0);
    k_agg<<<AGG_BLOCKS, 256>>>(0, sc_b, 2);

    // join: head needs both branches
    cudaStreamWaitEvent(0, e2, 0);
    k_headpool<<<NGRAPH, 256>>>(batch, fc1W, fc1b);
    k_loss<<<NGRAPH, 256>>>();
    k_final<<<1, 256>>>(fc2W, fc2b, (float*)d_out);
}

// round 15
// speedup vs baseline: 1.4857x; 1.4857x over previous
#include <cuda_runtime.h>
#include <cuda_bf16.h>
#include <cuda_fp16.h>
#include <math.h>
#include <stdint.h>

#define N_NODESC 100000
#define N_EDGESC 1600000
#define HID 128
#define NGRAPH 256
#define NLAYER 3
#define SCAN_BLOCKS ((N_NODESC + 1023) / 1024)   // 98
#define NT64 ((N_NODESC + 63) / 64)              // 1563

// prep kernel block ranges (W-split | zero-counts only)
#define WB ((NLAYER * HID * HID + 255) / 256)    // 192
#define ZB ((N_NODESC + 256) / 256)              // 392

// ---------------- scratch (static device globals; no allocation) ----------------
__device__ __half    g_h[2][(size_t)N_NODESC * HID];   // GEMM output (fp16)
__device__ uint32_t  g_xs[2][(size_t)N_NODESC * HID];  // activations, packed bf16 hi|lo
__device__ uint32_t  g_ws[2][NLAYER * HID * HID];      // W, packed bf16 hi|lo
__device__ float     g_dis[2][N_NODESC];
__device__ int       g_off[2][N_NODESC + 1];
__device__ int       g_cur[2][N_NODESC];
__device__ int2      g_ew[2][N_EDGESC];                // {src, enorm}
__device__ int       g_bsum[2][SCAN_BLOCKS + 1];
__device__ float     g_z[NGRAPH * HID];
__device__ float     g_scn[NGRAPH * HID];
__device__ float     g_fcn[NGRAPH * HID];
__device__ float     g_loss[2 * NGRAPH];

// ---------------- helpers ----------------
__device__ __forceinline__ uint32_t smem_u32(const void* p) {
    uint32_t a;
    asm("{ .reg .u64 t; cvta.to.shared.u64 t, %1; cvt.u32.u64 %0, t; }"
        : "=r"(a) : "l"(p));
    return a;
}
__device__ __forceinline__ uint32_t packsplit(float v) {
    __nv_bfloat16 h = __float2bfloat16_rn(v);
    float lo = v - __bfloat162float(h);
    __nv_bfloat16 l = __float2bfloat16_rn(lo);
    return (uint32_t)__bfloat16_as_ushort(h) |
           ((uint32_t)__bfloat16_as_ushort(l) << 16);
}
__device__ __forceinline__ float unpacksplit(uint32_t p) {
    return __bfloat162float(__ushort_as_bfloat16((unsigned short)(p & 0xffffu))) +
           __bfloat162float(__ushort_as_bfloat16((unsigned short)(p >> 16)));
}
#define LDSM_X4(r0, r1, r2, r3, addr) \
    asm volatile("ldmatrix.sync.aligned.m8n8.x4.shared.b16 {%0,%1,%2,%3}, [%4];" \
                 : "=r"(r0), "=r"(r1), "=r"(r2), "=r"(r3) : "r"(addr))
#define LDSM_X4T(r0, r1, r2, r3, addr) \
    asm volatile("ldmatrix.sync.aligned.m8n8.x4.trans.shared.b16 {%0,%1,%2,%3}, [%4];" \
                 : "=r"(r0), "=r"(r1), "=r"(r2), "=r"(r3) : "r"(addr))
#define MMA16816(c, a, b0, b1) \
    asm volatile("mma.sync.aligned.m16n8k16.row.col.f32.bf16.bf16.f32 " \
                 "{%0,%1,%2,%3}, {%4,%5,%6,%7}, {%8,%9}, {%0,%1,%2,%3};" \
                 : "+f"((c)[0]), "+f"((c)[1]), "+f"((c)[2]), "+f"((c)[3]) \
                 : "r"((a)[0]), "r"((a)[1]), "r"((a)[2]), "r"((a)[3]), \
                   "r"(b0), "r"(b1))

// ---------------- prep: w-split | zero counts ----------------
__global__ void k_prep(const float* __restrict__ scW, const float* __restrict__ fcW) {
    int b = blockIdx.y;
    int bx = blockIdx.x;
    if (bx < WB) {
        const float* W = b ? fcW : scW;
        int i = bx * 256 + threadIdx.x;
        if (i < NLAYER * HID * HID) g_ws[b][i] = packsplit(W[i]);
    } else {
        int i = (bx - WB) * 256 + threadIdx.x;
        if (i <= N_NODESC) g_off[b][i] = 0;
    }
}

// ---------------- CSR build ----------------
__global__ void k_hist(const int* __restrict__ sc_ei, const int* __restrict__ fc_ei) {
    int b = blockIdx.y;
    const int* dst = (b ? fc_ei : sc_ei) + N_EDGESC;
    for (int e = blockIdx.x * blockDim.x + threadIdx.x; e < N_EDGESC;
         e += gridDim.x * blockDim.x)
        atomicAdd(&g_off[b][dst[e]], 1);
}
__global__ void k_scan1() {
    __shared__ int ws[32];
    int b = blockIdx.y;
    int t = threadIdx.x;
    int lane = t & 31, w = t >> 5;
    int idx = blockIdx.x * 1024 + t;
    int v = (idx < N_NODESC) ? g_off[b][idx] : 0;
    if (idx < N_NODESC) g_dis[b][idx] = rsqrtf((float)v + 1.0f);
    int x = v;
#pragma unroll
    for (int off = 1; off < 32; off <<= 1) {
        int n = __shfl_up_sync(0xffffffffu, x, off);
        if (lane >= off) x += n;
    }
    if (lane == 31) ws[w] = x;
    __syncthreads();
    if (w == 0) {
        int y = ws[lane];
#pragma unroll
        for (int off = 1; off < 32; off <<= 1) {
            int n = __shfl_up_sync(0xffffffffu, y, off);
            if (lane >= off) y += n;
        }
        ws[lane] = y;
    }
    __syncthreads();
    int inc = x + ((w > 0) ? ws[w - 1] : 0);
    if (idx < N_NODESC) g_off[b][idx] = inc - v;
    if (t == 1023) g_bsum[b][blockIdx.x] = inc;
}
__global__ void k_scan3() {
    int b = blockIdx.y;
    int t = threadIdx.x;
    __shared__ int wsum[32];
    __shared__ int s_pref;
    int lane = t & 31, w = t >> 5;
    int v = (t < blockIdx.x) ? g_bsum[b][t] : 0;
#pragma unroll
    for (int off = 16; off > 0; off >>= 1)
        v += __shfl_down_sync(0xffffffffu, v, off);
    if (lane == 0) wsum[w] = v;
    __syncthreads();
    if (t == 0) {
        int s = 0;
#pragma unroll
        for (int i = 0; i < 32; i++) s += wsum[i];
        s_pref = s;
    }
    __syncthreads();
    int idx = blockIdx.x * 1024 + t;
    if (idx < N_NODESC) {
        int o = g_off[b][idx] + s_pref;
        g_off[b][idx] = o;
        g_cur[b][idx] = o;
    }
    if (blockIdx.x == 0 && t == 0) g_off[b][N_NODESC] = N_EDGESC;
}
__global__ void k_bucket(const int* __restrict__ sc_ei, const int* __restrict__ fc_ei) {
    int b = blockIdx.y;
    const int* src = (b ? fc_ei : sc_ei);
    const int* dst = src + N_EDGESC;
    for (int e = blockIdx.x * blockDim.x + threadIdx.x; e < N_EDGESC;
         e += gridDim.x * blockDim.x) {
        int d = dst[e];
        int s = src[e];
        int slot = atomicAdd(&g_cur[b][d], 1);
        float w = g_dis[b][s] * g_dis[b][d];
        g_ew[b][slot] = make_int2(s, __float_as_int(w));
    }
}

// ---------------- persistent tensor-core GEMM with A-prefetch ----------------
// L0=true: read fp32 inputs directly, split on the fly (no x-prep pass needed).
#define APITCH 136
#define BTILE_B (128 * APITCH * 2)     // 34816
#define ATILE_B (64 * APITCH * 2)      // 17408
#define OFF_BHI 0
#define OFF_BLO BTILE_B
#define OFF_AHI (2 * BTILE_B)
#define OFF_ALO (2 * BTILE_B + ATILE_B)
#define GEMM_SMEM (2 * BTILE_B + 2 * ATILE_B)   // 104448

template <bool L0>
__global__ void __launch_bounds__(256, 2)
k_gemm_mma(int layer, int nrows,
           const float4* __restrict__ sc_x, const float4* __restrict__ fc_x) {
    extern __shared__ char sm[];
    uint32_t base = smem_u32(sm);
    int b = blockIdx.y;
    int tid = threadIdx.x;
    const uint32_t* Xp = g_xs[b];
    const float4* Xf = b ? fc_x : sc_x;
    const uint32_t* Wp = g_ws[b] + layer * HID * HID;
    __half* Hp = g_h[b];

    for (int g = tid; g < 128 * 32; g += 256) {
        int k = g >> 5, q = g & 31;
        uint4 p = ((const uint4*)Wp)[k * 32 + q];
        uint32_t off = (uint32_t)(k * APITCH + q * 4) * 2u;
        *(uint2*)(sm + OFF_BHI + off) =
            make_uint2(__byte_perm(p.x, p.y, 0x5410), __byte_perm(p.z, p.w, 0x5410));
        *(uint2*)(sm + OFF_BLO + off) =
            make_uint2(__byte_perm(p.x, p.y, 0x7632), __byte_perm(p.z, p.w, 0x7632));
    }

    int w = tid >> 5, lane = tid & 31;
    int wm = w & 1, wn = w >> 1;
    int rbase = wm * 32, cbase = wn * 32;
    int a_r = lane & 15, a_c = (lane >> 4) * 8;
    int b_kr = ((lane >> 3) & 1) * 8 + (lane & 7), b_c = (lane >> 4) * 8;

    uint4 pre[8];
    {
        int r0 = blockIdx.x * 64;
#pragma unroll
        for (int i = 0; i < 8; ++i) {
            int g = tid + i * 256;
            int row = g >> 5, q = g & 31;
            int grow = r0 + row;
            if (grow < nrows) {
                if (L0) {
                    float4 v = Xf[(size_t)grow * 32 + q];
                    pre[i] = *(uint4*)&v;
                } else {
                    pre[i] = ((const uint4*)(Xp + (size_t)grow * HID))[q];
                }
            } else {
                pre[i] = make_uint4(0u, 0u, 0u, 0u);
            }
        }
    }

    for (int tile = blockIdx.x; tile < NT64; tile += gridDim.x) {
        int r0 = tile * 64;
        __syncthreads();
#pragma unroll
        for (int i = 0; i < 8; ++i) {
            int g = tid + i * 256;
            int row = g >> 5, q = g & 31;
            uint4 p;
            if (L0) {
                float4 v = *(float4*)&pre[i];
                p = make_uint4(packsplit(v.x), packsplit(v.y),
                               packsplit(v.z), packsplit(v.w));
            } else {
                p = pre[i];
            }
            uint32_t off = (uint32_t)(row * APITCH + q * 4) * 2u;
            *(uint2*)(sm + OFF_AHI + off) =
                make_uint2(__byte_perm(p.x, p.y, 0x5410), __byte_perm(p.z, p.w, 0x5410));
            *(uint2*)(sm + OFF_ALO + off) =
                make_uint2(__byte_perm(p.x, p.y, 0x7632), __byte_perm(p.z, p.w, 0x7632));
        }
        __syncthreads();

        int next = tile + gridDim.x;
        if (next < NT64) {
            int nr0 = next * 64;
#pragma unroll
            for (int i = 0; i < 8; ++i) {
                int g = tid + i * 256;
                int row = g >> 5, q = g & 31;
                int grow = nr0 + row;
                if (grow < nrows) {
                    if (L0) {
                        float4 v = Xf[(size_t)grow * 32 + q];
                        pre[i] = *(uint4*)&v;
                    } else {
                        pre[i] = ((const uint4*)(Xp + (size_t)grow * HID))[q];
                    }
                } else {
                    pre[i] = make_uint4(0u, 0u, 0u, 0u);
                }
            }
        }

        float acc[2][4][4];
#pragma unroll
        for (int m = 0; m < 2; m++)
#pragma unroll
            for (int n = 0; n < 4; n++)
#pragma unroll
                for (int c = 0; c < 4; c++) acc[m][n][c] = 0.f;

#pragma unroll
        for (int ks = 0; ks < 8; ++ks) {
            int k0 = ks * 16;
            uint32_t ahi[2][4], alo[2][4];
#pragma unroll
            for (int m = 0; m < 2; ++m) {
                uint32_t aoff =
                    (uint32_t)((rbase + m * 16 + a_r) * APITCH + k0 + a_c) * 2u;
                LDSM_X4(ahi[m][0], ahi[m][1], ahi[m][2], ahi[m][3], base + OFF_AHI + aoff);
                LDSM_X4(alo[m][0], alo[m][1], alo[m][2], alo[m][3], base + OFF_ALO + aoff);
            }
#pragma unroll
            for (int n2 = 0; n2 < 2; ++n2) {
                int n0 = cbase + n2 * 16;
                uint32_t boff = (uint32_t)((k0 + b_kr) * APITCH + n0 + b_c) * 2u;
                uint32_t bh0, bh1, bh2, bh3, bl0, bl1, bl2, bl3;
                LDSM_X4T(bh0, bh1, bh2, bh3, base + OFF_BHI + boff);
                LDSM_X4T(bl0, bl1, bl2, bl3, base + OFF_BLO + boff);
#pragma unroll
                for (int m = 0; m < 2; ++m) {
                    MMA16816(acc[m][n2 * 2], ahi[m], bh0, bh1);
                    MMA16816(acc[m][n2 * 2 + 1], ahi[m], bh2, bh3);
                    MMA16816(acc[m][n2 * 2], ahi[m], bl0, bl1);
                    MMA16816(acc[m][n2 * 2 + 1], ahi[m], bl2, bl3);
                    MMA16816(acc[m][n2 * 2], alo[m], bh0, bh1);
                    MMA16816(acc[m][n2 * 2 + 1], alo[m], bh2, bh3);
                }
            }
        }

#pragma unroll
        for (int m = 0; m < 2; ++m) {
            int rA = r0 + rbase + m * 16 + (lane >> 2);
            int rB = rA + 8;
#pragma unroll
            for (int ng = 0; ng < 4; ++ng) {
                int col = cbase + ng * 8 + (lane & 3) * 2;
                if (rA < nrows)
                    *(__half2*)(Hp + (size_t)rA * HID + col) =
                        __floats2half2_rn(acc[m][ng][0], acc[m][ng][1]);
                if (rB < nrows)
                    *(__half2*)(Hp + (size_t)rB * HID + col) =
                        __floats2half2_rn(acc[m][ng][2], acc[m][ng][3]);
            }
        }
    }
}

// ---------------- fused aggregation (8-way unrolled gather) ----------------
__global__ void __launch_bounds__(256)
k_agg(const float* __restrict__ sc_b, const float* __restrict__ fc_b, int layer) {
    int b = blockIdx.y;
    int node = (blockIdx.x * blockDim.x + threadIdx.x) >> 5;
    int lane = threadIdx.x & 31;
    if (node >= N_NODESC) return;
    const __half* Hp = g_h[b];
    const int2* ew = g_ew[b];
    const float* bias = (b ? fc_b : sc_b) + layer * HID;
    float dd = g_dis[b][node];
    int beg = g_off[b][node], end = g_off[b][node + 1];
    float ax = 0.f, ay = 0.f, az = 0.f, aw = 0.f;
    int e = beg;
    for (; e + 7 < end; e += 8) {
        int2 p[8];
        uint2 rv[8];
#pragma unroll
        for (int i = 0; i < 8; ++i) p[i] = ew[e + i];
#pragma unroll
        for (int i = 0; i < 8; ++i)
            rv[i] = *(const uint2*)(Hp + (size_t)p[i].x * HID + lane * 4);
#pragma unroll
        for (int i = 0; i < 8; ++i) {
            float wgt = __int_as_float(p[i].y);
            float2 f0 = __half22float2(*(__half2*)&rv[i].x);
            float2 f1 = __half22float2(*(__half2*)&rv[i].y);
            ax = fmaf(f0.x, wgt, ax); ay = fmaf(f0.y, wgt, ay);
            az = fmaf(f1.x, wgt, az); aw = fmaf(f1.y, wgt, aw);
        }
    }
    for (; e + 1 < end; e += 2) {
        int2 p0 = ew[e], p1 = ew[e + 1];
        uint2 r0v = *(const uint2*)(Hp + (size_t)p0.x * HID + lane * 4);
        uint2 r1v = *(const uint2*)(Hp + (size_t)p1.x * HID + lane * 4);
        float w0 = __int_as_float(p0.y), w1 = __int_as_float(p1.y);
        float2 f0 = __half22float2(*(__half2*)&r0v.x);
        float2 f1 = __half22float2(*(__half2*)&r0v.y);
        ax = fmaf(f0.x, w0, ax); ay = fmaf(f0.y, w0, ay);
        az = fmaf(f1.x, w0, az); aw = fmaf(f1.y, w0, aw);
        f0 = __half22float2(*(__half2*)&r1v.x);
        f1 = __half22float2(*(__half2*)&r1v.y);
        ax = fmaf(f0.x, w1, ax); ay = fmaf(f0.y, w1, ay);
        az = fmaf(f1.x, w1, az); aw = fmaf(f1.y, w1, aw);
    }
    if (e < end) {
        int2 p0 = ew[e];
        float w0 = __int_as_float(p0.y);
        uint2 r0v = *(const uint2*)(Hp + (size_t)p0.x * HID + lane * 4);
        float2 f0 = __half22float2(*(__half2*)&r0v.x);
        float2 f1 = __half22float2(*(__half2*)&r0v.y);
        ax = fmaf(f0.x, w0, ax); ay = fmaf(f0.y, w0, ay);
        az = fmaf(f1.x, w0, az); aw = fmaf(f1.y, w0, aw);
    }
    uint2 rs = *(const uint2*)(Hp + (size_t)node * HID + lane * 4);
    float2 s0 = __half22float2(*(__half2*)&rs.x);
    float2 s1 = __half22float2(*(__half2*)&rs.y);
    float sn = dd * dd;
    float4 bb = *(const float4*)(bias + lane * 4);
    ax = fmaxf(fmaf(s0.x, sn, ax) + bb.x, 0.f);
    ay = fmaxf(fmaf(s0.y, sn, ay) + bb.y, 0.f);
    az = fmaxf(fmaf(s1.x, sn, az) + bb.z, 0.f);
    aw = fmaxf(fmaf(s1.y, sn, aw) + bb.w, 0.f);
    uint4 st = make_uint4(packsplit(ax), packsplit(ay), packsplit(az), packsplit(aw));
    *(uint4*)(g_xs[b] + (size_t)node * HID + lane * 4) = st;
}

// ---------------- fused pool + head (block per graph) ----------------
__global__ void __launch_bounds__(128)
k_headpool(const int* __restrict__ batch, const float* __restrict__ fc1W,
           const float* __restrict__ fc1b) {
    int g = blockIdx.x, t = threadIdx.x;
    __shared__ int s_lo, s_hi;
    if (t == 0) {
        int lo = 0, hi = N_NODESC;
        while (lo < hi) { int m = (lo + hi) >> 1; if (batch[m] < g) lo = m + 1; else hi = m; }
        s_lo = lo;
    }
    if (t == 32) {
        int lo = 0, hi = N_NODESC;
        while (lo < hi) { int m = (lo + hi) >> 1; if (batch[m] < g + 1) lo = m + 1; else hi = m; }
        s_hi = lo;
    }
    __syncthreads();
    int lo = s_lo, hi = s_hi;
    const uint32_t* X0 = g_xs[0];
    const uint32_t* X1 = g_xs[1];
    float acc_sc = 0.f, acc_fc = 0.f;
    int n = lo;
    for (; n + 1 < hi; n += 2) {
        acc_sc += unpacksplit(X0[(size_t)n * HID + t]) +
                  unpacksplit(X0[(size_t)(n + 1) * HID + t]);
        acc_fc += unpacksplit(X1[(size_t)n * HID + t]) +
                  unpacksplit(X1[(size_t)(n + 1) * HID + t]);
    }
    for (; n < hi; ++n) {
        acc_sc += unpacksplit(X0[(size_t)n * HID + t]);
        acc_fc += unpacksplit(X1[(size_t)n * HID + t]);
    }

    __shared__ float s[256];
    __shared__ float red[128];
    __shared__ float inv_ns, inv_nf;
    s[t] = acc_sc;
    s[128 + t] = acc_fc;
    __syncthreads();
    red[t] = s[t] * s[t];
    __syncthreads();
    for (int off = 64; off > 0; off >>= 1) {
        if (t < off) red[t] += red[t + off];
        __syncthreads();
    }
    if (t == 0) inv_ns = 1.0f / fmaxf(sqrtf(red[0]), 1e-12f);
    __syncthreads();
    red[t] = s[128 + t] * s[128 + t];
    __syncthreads();
    for (int off = 64; off > 0; off >>= 1) {
        if (t < off) red[t] += red[t + off];
        __syncthreads();
    }
    if (t == 0) inv_nf = 1.0f / fmaxf(sqrtf(red[0]), 1e-12f);
    __syncthreads();
    float acc = 0.f;
#pragma unroll 8
    for (int k = 0; k < 256; k++) acc = fmaf(s[k], fc1W[k * HID + t], acc);
    acc += fc1b[t];
    g_z[g * HID + t] = fmaxf(acc, 0.f);
    g_scn[g * HID + t] = s[t] * inv_ns;
    g_fcn[g * HID + t] = s[128 + t] * inv_nf;
}

// ---------------- contrastive row losses ----------------
__global__ void k_loss() {
    int i = blockIdx.x, j = threadIdx.x;
    __shared__ float sni[HID], fni[HID];
    __shared__ float red[256];
    __shared__ float diag_sc, diag_fc, Msc, Mfc, Ssc, Sfc;
    if (j < HID) { sni[j] = g_scn[i * HID + j]; fni[j] = g_fcn[i * HID + j]; }
    __syncthreads();
    float dsf = 0.f, dss = 0.f, dfs = 0.f, dff = 0.f;
    const float* srow = &g_scn[j * HID];
    const float* frow = &g_fcn[j * HID];
#pragma unroll 4
    for (int k = 0; k < HID; k++) {
        float sj = srow[k], fj = frow[k], si = sni[k], fi = fni[k];
        dsf = fmaf(si, fj, dsf);
        dss = fmaf(si, sj, dss);
        dfs = fmaf(fi, sj, dfs);
        dff = fmaf(fi, fj, dff);
    }
    const float tt = 2.0f;
    float e1 = dsf * tt;
    float e2 = (j == i) ? 0.f : 0.8f * tt * dss;
    float f1 = dfs * tt;
    float f2 = (j == i) ? 0.f : 0.8f * tt * dff;
    if (j == i) { diag_sc = e1; diag_fc = f1; }
    red[j] = fmaxf(e1, e2);
    __syncthreads();
    for (int off = 128; off > 0; off >>= 1) {
        if (j < off) red[j] = fmaxf(red[j], red[j + off]);
        __syncthreads();
    }
    if (j == 0) Msc = red[0];
    __syncthreads();
    red[j] = expf(e1 - Msc) + expf(e2 - Msc);
    __syncthreads();
    for (int off = 128; off > 0; off >>= 1) {
        if (j < off) red[j] += red[j + off];
        __syncthreads();
    }
    if (j == 0) Ssc = red[0];
    __syncthreads();
    red[j] = fmaxf(f1, f2);
    __syncthreads();
    for (int off = 128; off > 0; off >>= 1) {
        if (j < off) red[j] = fmaxf(red[j], red[j + off]);
        __syncthreads();
    }
    if (j == 0) Mfc = red[0];
    __syncthreads();
    red[j] = expf(f1 - Mfc) + expf(f2 - Mfc);
    __syncthreads();
    for (int off = 128; off > 0; off >>= 1) {
        if (j < off) red[j] += red[j + off];
        __syncthreads();
    }
    if (j == 0) {
        Sfc = red[0];
        g_loss[i] = (Msc + logf(Ssc)) - diag_sc;
        g_loss[NGRAPH + i] = (Mfc + logf(Sfc)) - diag_fc;
    }
}

// ---------------- final ----------------
__global__ void k_final(const float* __restrict__ fc2W, const float* __restrict__ fc2b,
                        float* __restrict__ out) {
    __shared__ float red[256];
    __shared__ float scalar;
    int t = threadIdx.x;
    red[t] = g_loss[t] + g_loss[NGRAPH + t];
    __syncthreads();
    for (int off = 128; off > 0; off >>= 1) {
        if (t < off) red[t] += red[t + off];
        __syncthreads();
    }
    if (t == 0) scalar = red[0] / (2.0f * NGRAPH);
    __syncthreads();
    float l0 = fc2b[0], l1 = fc2b[1];
    const float* z = &g_z[t * HID];
#pragma unroll 4
    for (int k = 0; k < HID; k++) {
        float zv = z[k];
        l0 = fmaf(zv, fc2W[2 * k], l0);
        l1 = fmaf(zv, fc2W[2 * k + 1], l1);
    }
    float m = fmaxf(l0, l1);
    float lse = m + logf(expf(l0 - m) + expf(l1 - m));
    out[2 * t] = l0 - lse + scalar;
    out[2 * t + 1] = l1 - lse + scalar;
}

// ---------------- host side ----------------
extern "C" void kernel_launch(void* const* d_in, const int* in_sizes, int n_in,
                              void* d_out, int out_size) {
    const float *sc_x = 0, *fc_x = 0, *sc_W = 0, *sc_b = 0, *fc_W = 0, *fc_b = 0;
    const float *fc1W = 0, *fc1b = 0, *fc2W = 0, *fc2b = 0;
    const int *sc_ei = 0, *fc_ei = 0, *batch = 0;
    for (int i = 0; i < n_in; i++) {
        long s = in_sizes[i];
        const void* p = d_in[i];
        if (s == (long)N_NODESC * HID) {
            if (!sc_x) sc_x = (const float*)p; else fc_x = (const float*)p;
        } else if (s == 2L * N_EDGESC) {
            if (!sc_ei) sc_ei = (const int*)p; else fc_ei = (const int*)p;
        } else if (s == N_NODESC) {
            batch = (const int*)p;
        } else if (s == (long)NLAYER * HID * HID) {
            if (!sc_W) sc_W = (const float*)p; else fc_W = (const float*)p;
        } else if (s == (long)NLAYER * HID) {
            if (!sc_b) sc_b = (const float*)p; else fc_b = (const float*)p;
        } else if (s == 2L * HID * HID) {
            fc1W = (const float*)p;
        } else if (s == HID) {
            fc1b = (const float*)p;
        } else if (s == 2L * HID) {
            fc2W = (const float*)p;
        } else if (s == 2) {
            fc2b = (const float*)p;
        }
    }
    cudaFuncSetAttribute(k_gemm_mma<true>, cudaFuncAttributeMaxDynamicSharedMemorySize,
                         GEMM_SMEM);
    cudaFuncSetAttribute(k_gemm_mma<false>, cudaFuncAttributeMaxDynamicSharedMemorySize,
                         GEMM_SMEM);

    k_prep<<<dim3(WB + ZB, 2), 256>>>(sc_W, fc_W);
    k_hist<<<dim3(1024, 2), 256>>>(sc_ei, fc_ei);
    k_scan1<<<dim3(SCAN_BLOCKS, 2), 1024>>>();
    k_scan3<<<dim3(SCAN_BLOCKS, 2), 1024>>>();
    k_bucket<<<dim3(1024, 2), 256>>>(sc_ei, fc_ei);
    k_gemm_mma<true><<<dim3(148, 2), 256, GEMM_SMEM>>>(
        0, N_NODESC, (const float4*)sc_x, (const float4*)fc_x);
    k_agg<<<dim3((N_NODESC * 32 + 255) / 256, 2), 256>>>(sc_b, fc_b, 0);
    for (int l = 1; l < NLAYER; ++l) {
        k_gemm_mma<false><<<dim3(148, 2), 256, GEMM_SMEM>>>(l, N_NODESC, 0, 0);
        k_agg<<<dim3((N_NODESC * 32 + 255) / 256, 2), 256>>>(sc_b, fc_b, l);
    }
    k_headpool<<<NGRAPH, 128>>>(batch, fc1W, fc1b);
    k_loss<<<NGRAPH, 256>>>();
    k_final<<<1, 256>>>(fc2W, fc2b, (float*)d_out);
}

// round 16
// speedup vs baseline: 1.7050x; 1.1476x over previous
#include <cuda_runtime.h>
#include <cuda_bf16.h>
#include <cuda_fp16.h>
#include <math.h>
#include <stdint.h>

#define N_NODESC 100000
#define N_EDGESC 1600000
#define HID 128
#define NGRAPH 256
#define NLAYER 3
#define SCAN_BLOCKS ((N_NODESC + 1023) / 1024)   // 98
#define NT64 ((N_NODESC + 63) / 64)              // 1563

// prep kernel block ranges (W-split | zero-counts only)
#define WB ((NLAYER * HID * HID + 255) / 256)    // 192
#define ZB ((N_NODESC + 256) / 256)              // 392

// ---------------- scratch (static device globals; no allocation) ----------------
__device__ __half    g_h[2][(size_t)N_NODESC * HID];   // GEMM output (fp16)
__device__ uint32_t  g_xs[2][(size_t)N_NODESC * 64];   // activations, bf16x2 per word
__device__ uint32_t  g_ws[2][NLAYER * HID * HID];      // W, packed bf16 hi|lo
__device__ float     g_dis[2][N_NODESC];
__device__ int       g_off[2][N_NODESC + 1];
__device__ int       g_cur[2][N_NODESC];
__device__ int2      g_ew[2][N_EDGESC];                // {src, enorm}
__device__ int       g_bsum[2][SCAN_BLOCKS + 1];
__device__ float     g_z[NGRAPH * HID];
__device__ float     g_scn[NGRAPH * HID];
__device__ float     g_fcn[NGRAPH * HID];
__device__ float     g_loss[2 * NGRAPH];

// ---------------- helpers ----------------
__device__ __forceinline__ uint32_t smem_u32(const void* p) {
    uint32_t a;
    asm("{ .reg .u64 t; cvta.to.shared.u64 t, %1; cvt.u32.u64 %0, t; }"
        : "=r"(a) : "l"(p));
    return a;
}
__device__ __forceinline__ uint32_t packsplit(float v) {   // W: bf16 hi | bf16 lo
    __nv_bfloat16 h = __float2bfloat16_rn(v);
    float lo = v - __bfloat162float(h);
    __nv_bfloat16 l = __float2bfloat16_rn(lo);
    return (uint32_t)__bfloat16_as_ushort(h) |
           ((uint32_t)__bfloat16_as_ushort(l) << 16);
}
__device__ __forceinline__ uint32_t bf2(float a, float b) {  // low = a
    __nv_bfloat162 v = __floats2bfloat162_rn(a, b);
    return *(uint32_t*)&v;
}
__device__ __forceinline__ float bfx(uint32_t w, int hi) {
    unsigned short u = hi ? (unsigned short)(w >> 16) : (unsigned short)(w & 0xffffu);
    return __bfloat162float(__ushort_as_bfloat16(u));
}
#define LDSM_X4(r0, r1, r2, r3, addr) \
    asm volatile("ldmatrix.sync.aligned.m8n8.x4.shared.b16 {%0,%1,%2,%3}, [%4];" \
                 : "=r"(r0), "=r"(r1), "=r"(r2), "=r"(r3) : "r"(addr))
#define LDSM_X4T(r0, r1, r2, r3, addr) \
    asm volatile("ldmatrix.sync.aligned.m8n8.x4.trans.shared.b16 {%0,%1,%2,%3}, [%4];" \
                 : "=r"(r0), "=r"(r1), "=r"(r2), "=r"(r3) : "r"(addr))
#define MMA16816(c, a, b0, b1) \
    asm volatile("mma.sync.aligned.m16n8k16.row.col.f32.bf16.bf16.f32 " \
                 "{%0,%1,%2,%3}, {%4,%5,%6,%7}, {%8,%9}, {%0,%1,%2,%3};" \
                 : "+f"((c)[0]), "+f"((c)[1]), "+f"((c)[2]), "+f"((c)[3]) \
                 : "r"((a)[0]), "r"((a)[1]), "r"((a)[2]), "r"((a)[3]), \
                   "r"(b0), "r"(b1))

// ---------------- prep: w-split | zero counts ----------------
__global__ void k_prep(const float* __restrict__ scW, const float* __restrict__ fcW) {
    int b = blockIdx.y;
    int bx = blockIdx.x;
    if (bx < WB) {
        const float* W = b ? fcW : scW;
        int i = bx * 256 + threadIdx.x;
        if (i < NLAYER * HID * HID) g_ws[b][i] = packsplit(W[i]);
    } else {
        int i = (bx - WB) * 256 + threadIdx.x;
        if (i <= N_NODESC) g_off[b][i] = 0;
    }
}

// ---------------- CSR build ----------------
__global__ void k_hist(const int* __restrict__ sc_ei, const int* __restrict__ fc_ei) {
    int b = blockIdx.y;
    const int* dst = (b ? fc_ei : sc_ei) + N_EDGESC;
    for (int e = blockIdx.x * blockDim.x + threadIdx.x; e < N_EDGESC;
         e += gridDim.x * blockDim.x)
        atomicAdd(&g_off[b][dst[e]], 1);
}
__global__ void k_scan1() {
    __shared__ int ws[32];
    int b = blockIdx.y;
    int t = threadIdx.x;
    int lane = t & 31, w = t >> 5;
    int idx = blockIdx.x * 1024 + t;
    int v = (idx < N_NODESC) ? g_off[b][idx] : 0;
    if (idx < N_NODESC) g_dis[b][idx] = rsqrtf((float)v + 1.0f);
    int x = v;
#pragma unroll
    for (int off = 1; off < 32; off <<= 1) {
        int n = __shfl_up_sync(0xffffffffu, x, off);
        if (lane >= off) x += n;
    }
    if (lane == 31) ws[w] = x;
    __syncthreads();
    if (w == 0) {
        int y = ws[lane];
#pragma unroll
        for (int off = 1; off < 32; off <<= 1) {
            int n = __shfl_up_sync(0xffffffffu, y, off);
            if (lane >= off) y += n;
        }
        ws[lane] = y;
    }
    __syncthreads();
    int inc = x + ((w > 0) ? ws[w - 1] : 0);
    if (idx < N_NODESC) g_off[b][idx] = inc - v;
    if (t == 1023) g_bsum[b][blockIdx.x] = inc;
}
__global__ void k_scan3() {
    int b = blockIdx.y;
    int t = threadIdx.x;
    __shared__ int wsum[32];
    __shared__ int s_pref;
    int lane = t & 31, w = t >> 5;
    int v = (t < blockIdx.x) ? g_bsum[b][t] : 0;
#pragma unroll
    for (int off = 16; off > 0; off >>= 1)
        v += __shfl_down_sync(0xffffffffu, v, off);
    if (lane == 0) wsum[w] = v;
    __syncthreads();
    if (t == 0) {
        int s = 0;
#pragma unroll
        for (int i = 0; i < 32; i++) s += wsum[i];
        s_pref = s;
    }
    __syncthreads();
    int idx = blockIdx.x * 1024 + t;
    if (idx < N_NODESC) {
        int o = g_off[b][idx] + s_pref;
        g_off[b][idx] = o;
        g_cur[b][idx] = o;
    }
    if (blockIdx.x == 0 && t == 0) g_off[b][N_NODESC] = N_EDGESC;
}
__global__ void k_bucket(const int* __restrict__ sc_ei, const int* __restrict__ fc_ei) {
    int b = blockIdx.y;
    const int* src = (b ? fc_ei : sc_ei);
    const int* dst = src + N_EDGESC;
    for (int e = blockIdx.x * blockDim.x + threadIdx.x; e < N_EDGESC;
         e += gridDim.x * blockDim.x) {
        int d = dst[e];
        int s = src[e];
        int slot = atomicAdd(&g_cur[b][d], 1);
        float w = g_dis[b][s] * g_dis[b][d];
        g_ew[b][slot] = make_int2(s, __float_as_int(w));
    }
}

// ---------------- persistent tensor-core GEMM, 2-term split (A bf16) -----------
#define APITCH 136
#define BTILE_B (128 * APITCH * 2)     // 34816
#define ATILE_B (64 * APITCH * 2)      // 17408
#define OFF_BHI 0
#define OFF_BLO BTILE_B
#define OFF_AHI (2 * BTILE_B)
#define GEMM_SMEM (2 * BTILE_B + ATILE_B)   // 87040

template <bool L0>
__global__ void __launch_bounds__(256, 2)
k_gemm_mma(int layer, int nrows,
           const float4* __restrict__ sc_x, const float4* __restrict__ fc_x) {
    extern __shared__ char sm[];
    uint32_t base = smem_u32(sm);
    int b = blockIdx.y;
    int tid = threadIdx.x;
    const uint32_t* Xp = g_xs[b];
    const float4* Xf = b ? fc_x : sc_x;
    const uint32_t* Wp = g_ws[b] + layer * HID * HID;
    __half* Hp = g_h[b];

    // unpack W -> Bhi/Blo once per CTA
    for (int g = tid; g < 128 * 32; g += 256) {
        int k = g >> 5, q = g & 31;
        uint4 p = ((const uint4*)Wp)[k * 32 + q];
        uint32_t off = (uint32_t)(k * APITCH + q * 4) * 2u;
        *(uint2*)(sm + OFF_BHI + off) =
            make_uint2(__byte_perm(p.x, p.y, 0x5410), __byte_perm(p.z, p.w, 0x5410));
        *(uint2*)(sm + OFF_BLO + off) =
            make_uint2(__byte_perm(p.x, p.y, 0x7632), __byte_perm(p.z, p.w, 0x7632));
    }

    int w = tid >> 5, lane = tid & 31;
    int wm = w & 1, wn = w >> 1;
    int rbase = wm * 32, cbase = wn * 32;
    int a_r = lane & 15, a_c = (lane >> 4) * 8;
    int b_kr = ((lane >> 3) & 1) * 8 + (lane & 7), b_c = (lane >> 4) * 8;

    // A prefetch: 1024 tasks/tile (64 rows x 16 8-col groups), 4 tasks/thread.
    // non-L0: pre[0..3] hold bf16x8 (uint4). L0: pre[2i],pre[2i+1] hold 2 float4s.
    uint4 pre[8];
    {
        int r0 = blockIdx.x * 64;
#pragma unroll
        for (int i = 0; i < 4; ++i) {
            int g = tid + i * 256;
            int row = g >> 4, q = g & 15;
            int grow = r0 + row;
            if (grow < nrows) {
                if (L0) {
                    float4 v0 = Xf[(size_t)grow * 32 + q * 2];
                    float4 v1 = Xf[(size_t)grow * 32 + q * 2 + 1];
                    pre[2 * i] = *(uint4*)&v0;
                    pre[2 * i + 1] = *(uint4*)&v1;
                } else {
                    pre[i] = ((const uint4*)(Xp + (size_t)grow * 64))[q];
                }
            } else {
                pre[i] = make_uint4(0u, 0u, 0u, 0u);
                if (L0) pre[2 * i] = pre[2 * i + 1] = make_uint4(0u, 0u, 0u, 0u);
            }
        }
    }

    for (int tile = blockIdx.x; tile < NT64; tile += gridDim.x) {
        int r0 = tile * 64;
        __syncthreads();
#pragma unroll
        for (int i = 0; i < 4; ++i) {
            int g = tid + i * 256;
            int row = g >> 4, q = g & 15;
            uint4 out;
            if (L0) {
                float4 v0 = *(float4*)&pre[2 * i];
                float4 v1 = *(float4*)&pre[2 * i + 1];
                out.x = bf2(v0.x, v0.y); out.y = bf2(v0.z, v0.w);
                out.z = bf2(v1.x, v1.y); out.w = bf2(v1.z, v1.w);
            } else {
                out = pre[i];
            }
            *(uint4*)(sm + OFF_AHI + (uint32_t)(row * APITCH + q * 8) * 2u) = out;
        }
        __syncthreads();

        int next = tile + gridDim.x;
        if (next < NT64) {
            int nr0 = next * 64;
#pragma unroll
            for (int i = 0; i < 4; ++i) {
                int g = tid + i * 256;
                int row = g >> 4, q = g & 15;
                int grow = nr0 + row;
                if (grow < nrows) {
                    if (L0) {
                        float4 v0 = Xf[(size_t)grow * 32 + q * 2];
                        float4 v1 = Xf[(size_t)grow * 32 + q * 2 + 1];
                        pre[2 * i] = *(uint4*)&v0;
                        pre[2 * i + 1] = *(uint4*)&v1;
                    } else {
                        pre[i] = ((const uint4*)(Xp + (size_t)grow * 64))[q];
                    }
                } else {
                    pre[i] = make_uint4(0u, 0u, 0u, 0u);
                    if (L0) pre[2 * i] = pre[2 * i + 1] = make_uint4(0u, 0u, 0u, 0u);
                }
            }
        }

        float acc[2][4][4];
#pragma unroll
        for (int m = 0; m < 2; m++)
#pragma unroll
            for (int n = 0; n < 4; n++)
#pragma unroll
                for (int c = 0; c < 4; c++) acc[m][n][c] = 0.f;

#pragma unroll
        for (int ks = 0; ks < 8; ++ks) {
            int k0 = ks * 16;
            uint32_t ahi[2][4];
#pragma unroll
            for (int m = 0; m < 2; ++m) {
                uint32_t aoff =
                    (uint32_t)((rbase + m * 16 + a_r) * APITCH + k0 + a_c) * 2u;
                LDSM_X4(ahi[m][0], ahi[m][1], ahi[m][2], ahi[m][3], base + OFF_AHI + aoff);
            }
#pragma unroll
            for (int n2 = 0; n2 < 2; ++n2) {
                int n0 = cbase + n2 * 16;
                uint32_t boff = (uint32_t)((k0 + b_kr) * APITCH + n0 + b_c) * 2u;
                uint32_t bh0, bh1, bh2, bh3, bl0, bl1, bl2, bl3;
                LDSM_X4T(bh0, bh1, bh2, bh3, base + OFF_BHI + boff);
                LDSM_X4T(bl0, bl1, bl2, bl3, base + OFF_BLO + boff);
#pragma unroll
                for (int m = 0; m < 2; ++m) {
                    MMA16816(acc[m][n2 * 2], ahi[m], bh0, bh1);
                    MMA16816(acc[m][n2 * 2 + 1], ahi[m], bh2, bh3);
                    MMA16816(acc[m][n2 * 2], ahi[m], bl0, bl1);
                    MMA16816(acc[m][n2 * 2 + 1], ahi[m], bl2, bl3);
                }
            }
        }

#pragma unroll
        for (int m = 0; m < 2; ++m) {
            int rA = r0 + rbase + m * 16 + (lane >> 2);
            int rB = rA + 8;
#pragma unroll
            for (int ng = 0; ng < 4; ++ng) {
                int col = cbase + ng * 8 + (lane & 3) * 2;
                if (rA < nrows)
                    *(__half2*)(Hp + (size_t)rA * HID + col) =
                        __floats2half2_rn(acc[m][ng][0], acc[m][ng][1]);
                if (rB < nrows)
                    *(__half2*)(Hp + (size_t)rB * HID + col) =
                        __floats2half2_rn(acc[m][ng][2], acc[m][ng][3]);
            }
        }
    }
}

// ---------------- fused aggregation (8-way unrolled gather, bf16x2 xs store) ----
__global__ void __launch_bounds__(256)
k_agg(const float* __restrict__ sc_b, const float* __restrict__ fc_b, int layer) {
    int b = blockIdx.y;
    int node = (blockIdx.x * blockDim.x + threadIdx.x) >> 5;
    int lane = threadIdx.x & 31;
    if (node >= N_NODESC) return;
    const __half* Hp = g_h[b];
    const int2* ew = g_ew[b];
    const float* bias = (b ? fc_b : sc_b) + layer * HID;
    float dd = g_dis[b][node];
    int beg = g_off[b][node], end = g_off[b][node + 1];
    float ax = 0.f, ay = 0.f, az = 0.f, aw = 0.f;
    int e = beg;
    for (; e + 7 < end; e += 8) {
        int2 p[8];
        uint2 rv[8];
#pragma unroll
        for (int i = 0; i < 8; ++i) p[i] = ew[e + i];
#pragma unroll
        for (int i = 0; i < 8; ++i)
            rv[i] = *(const uint2*)(Hp + (size_t)p[i].x * HID + lane * 4);
#pragma unroll
        for (int i = 0; i < 8; ++i) {
            float wgt = __int_as_float(p[i].y);
            float2 f0 = __half22float2(*(__half2*)&rv[i].x);
            float2 f1 = __half22float2(*(__half2*)&rv[i].y);
            ax = fmaf(f0.x, wgt, ax); ay = fmaf(f0.y, wgt, ay);
            az = fmaf(f1.x, wgt, az); aw = fmaf(f1.y, wgt, aw);
        }
    }
    for (; e + 1 < end; e += 2) {
        int2 p0 = ew[e], p1 = ew[e + 1];
        uint2 r0v = *(const uint2*)(Hp + (size_t)p0.x * HID + lane * 4);
        uint2 r1v = *(const uint2*)(Hp + (size_t)p1.x * HID + lane * 4);
        float w0 = __int_as_float(p0.y), w1 = __int_as_float(p1.y);
        float2 f0 = __half22float2(*(__half2*)&r0v.x);
        float2 f1 = __half22float2(*(__half2*)&r0v.y);
        ax = fmaf(f0.x, w0, ax); ay = fmaf(f0.y, w0, ay);
        az = fmaf(f1.x, w0, az); aw = fmaf(f1.y, w0, aw);
        f0 = __half22float2(*(__half2*)&r1v.x);
        f1 = __half22float2(*(__half2*)&r1v.y);
        ax = fmaf(f0.x, w1, ax); ay = fmaf(f0.y, w1, ay);
        az = fmaf(f1.x, w1, az); aw = fmaf(f1.y, w1, aw);
    }
    if (e < end) {
        int2 p0 = ew[e];
        float w0 = __int_as_float(p0.y);
        uint2 r0v = *(const uint2*)(Hp + (size_t)p0.x * HID + lane * 4);
        float2 f0 = __half22float2(*(__half2*)&r0v.x);
        float2 f1 = __half22float2(*(__half2*)&r0v.y);
        ax = fmaf(f0.x, w0, ax); ay = fmaf(f0.y, w0, ay);
        az = fmaf(f1.x, w0, az); aw = fmaf(f1.y, w0, aw);
    }
    uint2 rs = *(const uint2*)(Hp + (size_t)node * HID + lane * 4);
    float2 s0 = __half22float2(*(__half2*)&rs.x);
    float2 s1 = __half22float2(*(__half2*)&rs.y);
    float sn = dd * dd;
    float4 bb = *(const float4*)(bias + lane * 4);
    ax = fmaxf(fmaf(s0.x, sn, ax) + bb.x, 0.f);
    ay = fmaxf(fmaf(s0.y, sn, ay) + bb.y, 0.f);
    az = fmaxf(fmaf(s1.x, sn, az) + bb.z, 0.f);
    aw = fmaxf(fmaf(s1.y, sn, aw) + bb.w, 0.f);
    *(uint2*)(g_xs[b] + (size_t)node * 64 + lane * 2) =
        make_uint2(bf2(ax, ay), bf2(az, aw));
}

// ---------------- fused pool + head (block per graph) ----------------
__global__ void __launch_bounds__(128)
k_headpool(const int* __restrict__ batch, const float* __restrict__ fc1W,
           const float* __restrict__ fc1b) {
    int g = blockIdx.x, t = threadIdx.x;
    __shared__ int s_lo, s_hi;
    if (t == 0) {
        int lo = 0, hi = N_NODESC;
        while (lo < hi) { int m = (lo + hi) >> 1; if (batch[m] < g) lo = m + 1; else hi = m; }
        s_lo = lo;
    }
    if (t == 32) {
        int lo = 0, hi = N_NODESC;
        while (lo < hi) { int m = (lo + hi) >> 1; if (batch[m] < g + 1) lo = m + 1; else hi = m; }
        s_hi = lo;
    }
    __syncthreads();
    int lo = s_lo, hi = s_hi;
    const uint32_t* X0 = g_xs[0];
    const uint32_t* X1 = g_xs[1];
    int wi = t >> 1, hiSel = t & 1;
    float acc_sc = 0.f, acc_fc = 0.f;
    int n = lo;
    for (; n + 1 < hi; n += 2) {
        acc_sc += bfx(X0[(size_t)n * 64 + wi], hiSel) +
                  bfx(X0[(size_t)(n + 1) * 64 + wi], hiSel);
        acc_fc += bfx(X1[(size_t)n * 64 + wi], hiSel) +
                  bfx(X1[(size_t)(n + 1) * 64 + wi], hiSel);
    }
    for (; n < hi; ++n) {
        acc_sc += bfx(X0[(size_t)n * 64 + wi], hiSel);
        acc_fc += bfx(X1[(size_t)n * 64 + wi], hiSel);
    }

    __shared__ float s[256];
    __shared__ float red[128];
    __shared__ float inv_ns, inv_nf;
    s[t] = acc_sc;
    s[128 + t] = acc_fc;
    __syncthreads();
    red[t] = s[t] * s[t];
    __syncthreads();
    for (int off = 64; off > 0; off >>= 1) {
        if (t < off) red[t] += red[t + off];
        __syncthreads();
    }
    if (t == 0) inv_ns = 1.0f / fmaxf(sqrtf(red[0]), 1e-12f);
    __syncthreads();
    red[t] = s[128 + t] * s[128 + t];
    __syncthreads();
    for (int off = 64; off > 0; off >>= 1) {
        if (t < off) red[t] += red[t + off];
        __syncthreads();
    }
    if (t == 0) inv_nf = 1.0f / fmaxf(sqrtf(red[0]), 1e-12f);
    __syncthreads();
    float acc = 0.f;
#pragma unroll 8
    for (int k = 0; k < 256; k++) acc = fmaf(s[k], fc1W[k * HID + t], acc);
    acc += fc1b[t];
    g_z[g * HID + t] = fmaxf(acc, 0.f);
    g_scn[g * HID + t] = s[t] * inv_ns;
    g_fcn[g * HID + t] = s[128 + t] * inv_nf;
}

// ---------------- contrastive row losses ----------------
__global__ void k_loss() {
    int i = blockIdx.x, j = threadIdx.x;
    __shared__ float sni[HID], fni[HID];
    __shared__ float red[256];
    __shared__ float diag_sc, diag_fc, Msc, Mfc, Ssc, Sfc;
    if (j < HID) { sni[j] = g_scn[i * HID + j]; fni[j] = g_fcn[i * HID + j]; }
    __syncthreads();
    float dsf = 0.f, dss = 0.f, dfs = 0.f, dff = 0.f;
    const float* srow = &g_scn[j * HID];
    const float* frow = &g_fcn[j * HID];
#pragma unroll 4
    for (int k = 0; k < HID; k++) {
        float sj = srow[k], fj = frow[k], si = sni[k], fi = fni[k];
        dsf = fmaf(si, fj, dsf);
        dss = fmaf(si, sj, dss);
        dfs = fmaf(fi, sj, dfs);
        dff = fmaf(fi, fj, dff);
    }
    const float tt = 2.0f;
    float e1 = dsf * tt;
    float e2 = (j == i) ? 0.f : 0.8f * tt * dss;
    float f1 = dfs * tt;
    float f2 = (j == i) ? 0.f : 0.8f * tt * dff;
    if (j == i) { diag_sc = e1; diag_fc = f1; }
    red[j] = fmaxf(e1, e2);
    __syncthreads();
    for (int off = 128; off > 0; off >>= 1) {
        if (j < off) red[j] = fmaxf(red[j], red[j + off]);
        __syncthreads();
    }
    if (j == 0) Msc = red[0];
    __syncthreads();
    red[j] = expf(e1 - Msc) + expf(e2 - Msc);
    __syncthreads();
    for (int off = 128; off > 0; off >>= 1) {
        if (j < off) red[j] += red[j + off];
        __syncthreads();
    }
    if (j == 0) Ssc = red[0];
    __syncthreads();
    red[j] = fmaxf(f1, f2);
    __syncthreads();
    for (int off = 128; off > 0; off >>= 1) {
        if (j < off) red[j] = fmaxf(red[j], red[j + off]);
        __syncthreads();
    }
    if (j == 0) Mfc = red[0];
    __syncthreads();
    red[j] = expf(f1 - Mfc) + expf(f2 - Mfc);
    __syncthreads();
    for (int off = 128; off > 0; off >>= 1) {
        if (j < off) red[j] += red[j + off];
        __syncthreads();
    }
    if (j == 0) {
        Sfc = red[0];
        g_loss[i] = (Msc + logf(Ssc)) - diag_sc;
        g_loss[NGRAPH + i] = (Mfc + logf(Sfc)) - diag_fc;
    }
}

// ---------------- final ----------------
__global__ void k_final(const float* __restrict__ fc2W, const float* __restrict__ fc2b,
                        float* __restrict__ out) {
    __shared__ float red[256];
    __shared__ float scalar;
    int t = threadIdx.x;
    red[t] = g_loss[t] + g_loss[NGRAPH + t];
    __syncthreads();
    for (int off = 128; off > 0; off >>= 1) {
        if (t < off) red[t] += red[t + off];
        __syncthreads();
    }
    if (t == 0) scalar = red[0] / (2.0f * NGRAPH);
    __syncthreads();
    float l0 = fc2b[0], l1 = fc2b[1];
    const float* z = &g_z[t * HID];
#pragma unroll 4
    for (int k = 0; k < HID; k++) {
        float zv = z[k];
        l0 = fmaf(zv, fc2W[2 * k], l0);
        l1 = fmaf(zv, fc2W[2 * k + 1], l1);
    }
    float m = fmaxf(l0, l1);
    float lse = m + logf(expf(l0 - m) + expf(l1 - m));
    out[2 * t] = l0 - lse + scalar;
    out[2 * t + 1] = l1 - lse + scalar;
}

// ---------------- host side ----------------
extern "C" void kernel_launch(void* const* d_in, const int* in_sizes, int n_in,
                              void* d_out, int out_size) {
    const float *sc_x = 0, *fc_x = 0, *sc_W = 0, *sc_b = 0, *fc_W = 0, *fc_b = 0;
    const float *fc1W = 0, *fc1b = 0, *fc2W = 0, *fc2b = 0;
    const int *sc_ei = 0, *fc_ei = 0, *batch = 0;
    for (int i = 0; i < n_in; i++) {
        long s = in_sizes[i];
        const void* p = d_in[i];
        if (s == (long)N_NODESC * HID) {
            if (!sc_x) sc_x = (const float*)p; else fc_x = (const float*)p;
        } else if (s == 2L * N_EDGESC) {
            if (!sc_ei) sc_ei = (const int*)p; else fc_ei = (const int*)p;
        } else if (s == N_NODESC) {
            batch = (const int*)p;
        } else if (s == (long)NLAYER * HID * HID) {
            if (!sc_W) sc_W = (const float*)p; else fc_W = (const float*)p;
        } else if (s == (long)NLAYER * HID) {
            if (!sc_b) sc_b = (const float*)p; else fc_b = (const float*)p;
        } else if (s == 2L * HID * HID) {
            fc1W = (const float*)p;
        } else if (s == HID) {
            fc1b = (const float*)p;
        } else if (s == 2L * HID) {
            fc2W = (const float*)p;
        } else if (s == 2) {
            fc2b = (const float*)p;
        }
    }
    cudaFuncSetAttribute(k_gemm_mma<true>, cudaFuncAttributeMaxDynamicSharedMemorySize,
                         GEMM_SMEM);
    cudaFuncSetAttribute(k_gemm_mma<false>, cudaFuncAttributeMaxDynamicSharedMemorySize,
                         GEMM_SMEM);

    k_prep<<<dim3(WB + ZB, 2), 256>>>(sc_W, fc_W);
    k_hist<<<dim3(1024, 2), 256>>>(sc_ei, fc_ei);
    k_scan1<<<dim3(SCAN_BLOCKS, 2), 1024>>>();
    k_scan3<<<dim3(SCAN_BLOCKS, 2), 1024>>>();
    k_bucket<<<dim3(1024, 2), 256>>>(sc_ei, fc_ei);
    k_gemm_mma<true><<<dim3(148, 2), 256, GEMM_SMEM>>>(
        0, N_NODESC, (const float4*)sc_x, (const float4*)fc_x);
    k_agg<<<dim3((N_NODESC * 32 + 255) / 256, 2), 256>>>(sc_b, fc_b, 0);
    for (int l = 1; l < NLAYER; ++l) {
        k_gemm_mma<false><<<dim3(148, 2), 256, GEMM_SMEM>>>(l, N_NODESC, 0, 0);
        k_agg<<<dim3((N_NODESC * 32 + 255) / 256, 2), 256>>>(sc_b, fc_b, l);
    }
    k_headpool<<<NGRAPH, 128>>>(batch, fc1W, fc1b);
    k_loss<<<NGRAPH, 256>>>();
    k_final<<<1, 256>>>(fc2W, fc2b, (float*)d_out);
}